// round 7
// baseline (speedup 1.0000x reference)
#include <cuda_runtime.h>
#include <cuda_bf16.h>
#include <math.h>
#include <stdint.h>

#define NLAY 6
#define DIM 256
#define VOC 1024
#define SEQ 48
#define BSZ 64
#define LT 49
#define NB 64          // persistent decoder blocks

__device__ float g_pe[LT * DIM];
__device__ unsigned g_keys[96];
__device__ float g_xA[3072 * DIM];
__device__ float g_xB[3072 * DIM];
__device__ float g_qkvE[3072 * 768];
__device__ float g_oE[3072 * DIM];
__device__ float g_tE[3072 * DIM];
__device__ float g_ffE[3072 * 1024];
__device__ float g_mem[3072 * DIM];
__device__ float g_ckv[NLAY * 3072 * 512];
__device__ float g_skv[(size_t)NLAY * BSZ * LT * 512];
__device__ float g_y[BSZ * DIM];
__device__ float g_qkv[BSZ * 768];
__device__ float g_ff[BSZ * 1024];
__device__ float g_part[4 * BSZ * DIM];
__device__ float g_h[BSZ * DIM];
__device__ unsigned g_cnt = 0;
__device__ unsigned g_gen = 0;

__device__ __forceinline__ float wsum(float s) {
#pragma unroll
    for (int o = 16; o; o >>= 1) s += __shfl_xor_sync(0xffffffffu, s, o);
    return s;
}

__device__ __forceinline__ uint2 tf2x32(unsigned k0, unsigned k1, unsigned x0, unsigned x1) {
    unsigned ks0 = k0, ks1 = k1, ks2 = k0 ^ k1 ^ 0x1BD11BDAu;
    x0 += ks0; x1 += ks1;
#define TFR(r) { x0 += x1; x1 = (x1 << (r)) | (x1 >> (32 - (r))); x1 ^= x0; }
    TFR(13) TFR(15) TFR(26) TFR(6)  x0 += ks1; x1 += ks2 + 1u;
    TFR(17) TFR(29) TFR(16) TFR(24) x0 += ks2; x1 += ks0 + 2u;
    TFR(13) TFR(15) TFR(26) TFR(6)  x0 += ks0; x1 += ks1 + 3u;
    TFR(17) TFR(29) TFR(16) TFR(24) x0 += ks1; x1 += ks2 + 4u;
    TFR(13) TFR(15) TFR(26) TFR(6)  x0 += ks2; x1 += ks0 + 5u;
#undef TFR
    return make_uint2(x0, x1);
}

// ---------------- setup / encoder kernels ----------------
__global__ void k_pe() {
    int p = blockIdx.x, j = threadIdx.x;
    float dv = expf((float)(2 * j) * (-logf(10000.0f) / 256.0f));
    float a = (float)p * dv;
    g_pe[p * DIM + 2 * j] = sinf(a);
    g_pe[p * DIM + 2 * j + 1] = cosf(a);
}

// jax_threefry_partitionable=True (default since jax 0.4.36):
// split(key,48): subkey[j] = threefry2x32(k1,k2, hi=0, lo=j) -> (x, y)
__global__ void k_keys() {
    int j = threadIdx.x;
    if (j < 48) {
        uint2 r = tf2x32(0u, 42u, 0u, (unsigned)j);
        g_keys[2 * j] = r.x; g_keys[2 * j + 1] = r.y;
    }
}

__global__ void k_embed(const int* __restrict__ xc, const int* __restrict__ xk,
                        const float* __restrict__ emb) {
    int row = blockIdx.x, t = threadIdx.x;
    int b = row / SEQ, s = row % SEQ;
    int idx = (s < 32) ? xc[b * 32 + s] : xk[b * 16 + (s - 32)];
    g_xA[(size_t)row * DIM + t] = emb[((size_t)s * VOC + idx) * DIM + t] + g_pe[s * DIM + t];
}

__global__ void k_gemm(const float* __restrict__ A, const float* __restrict__ W,
                       const float* __restrict__ bias, float* __restrict__ C,
                       int M, int N, int K, int relu) {
    __shared__ float sA[16][65], sB[16][65];
    int m0 = blockIdx.y * 64, n0 = blockIdx.x * 64;
    int tid = threadIdx.x;
    int r = tid >> 2, kk = (tid & 3) * 4;
    int ty = tid >> 4, tx = tid & 15;
    float acc[4][4] = {};
    for (int kb = 0; kb < K; kb += 16) {
        const float* Ap = A + (size_t)(m0 + r) * K + kb + kk;
        const float* Bp = W + (size_t)(n0 + r) * K + kb + kk;
#pragma unroll
        for (int u = 0; u < 4; u++) { sA[kk + u][r] = Ap[u]; sB[kk + u][r] = Bp[u]; }
        __syncthreads();
#pragma unroll
        for (int k = 0; k < 16; k++) {
            float a[4], b[4];
#pragma unroll
            for (int i = 0; i < 4; i++) a[i] = sA[k][ty * 4 + i];
#pragma unroll
            for (int j = 0; j < 4; j++) b[j] = sB[k][tx * 4 + j];
#pragma unroll
            for (int i = 0; i < 4; i++)
#pragma unroll
                for (int j = 0; j < 4; j++) acc[i][j] = fmaf(a[i], b[j], acc[i][j]);
        }
        __syncthreads();
    }
#pragma unroll
    for (int i = 0; i < 4; i++) {
        int m = m0 + ty * 4 + i;
#pragma unroll
        for (int j = 0; j < 4; j++) {
            int n = n0 + tx * 4 + j;
            float c = acc[i][j] + (bias ? bias[n] : 0.f);
            if (relu) c = fmaxf(c, 0.f);
            C[(size_t)m * N + n] = c;
        }
    }
}

__global__ void k_addln(const float* __restrict__ a, const float* __restrict__ b,
                        const float* __restrict__ w, const float* __restrict__ wb,
                        float* __restrict__ out) {
    int row = blockIdx.x, t = threadIdx.x;
    __shared__ float red[16];
    __shared__ float sm, srs;
    float v = a[(size_t)row * DIM + t] + (b ? b[(size_t)row * DIM + t] : 0.f);
    float s = wsum(v), q = wsum(v * v);
    int lane = t & 31, wd = t >> 5;
    if (lane == 0) { red[wd] = s; red[8 + wd] = q; }
    __syncthreads();
    if (t == 0) {
        float S = 0.f, Q = 0.f;
        for (int i = 0; i < 8; i++) { S += red[i]; Q += red[8 + i]; }
        float m = S * (1.f / 256.f);
        sm = m; srs = rsqrtf(Q * (1.f / 256.f) - m * m + 1e-5f);
    }
    __syncthreads();
    out[(size_t)row * DIM + t] = (v - sm) * srs * w[t] + wb[t];
}

__global__ void k_enc_attn(const float* __restrict__ QKV, float* __restrict__ O) {
    int b = blockIdx.x >> 3, h = blockIdx.x & 7, tid = threadIdx.x;
    __shared__ float sQ[48][33], sK[48][33], sV[48][33], sS[48][49];
    for (int i = tid; i < 48 * 32; i += 256) {
        int s = i >> 5, d = i & 31;
        size_t base = (size_t)(b * 48 + s) * 768;
        sQ[s][d] = QKV[base + h * 32 + d];
        sK[s][d] = QKV[base + 256 + h * 32 + d];
        sV[s][d] = QKV[base + 512 + h * 32 + d];
    }
    __syncthreads();
    const float sc = 0.17677669529663687f;
    for (int i = tid; i < 48 * 48; i += 256) {
        int q = i / 48, k = i % 48;
        float s = 0.f;
#pragma unroll
        for (int d = 0; d < 32; d++) s = fmaf(sQ[q][d], sK[k][d], s);
        sS[q][k] = s * sc;
    }
    __syncthreads();
    int lane = tid & 31, wd = tid >> 5;
    for (int q = wd; q < 48; q += 8) {
        float v1 = (lane < 48) ? sS[q][lane] : -1e30f;
        float v2 = (lane + 32 < 48) ? sS[q][lane + 32] : -1e30f;
        float mx = fmaxf(v1, v2);
#pragma unroll
        for (int o = 16; o; o >>= 1) mx = fmaxf(mx, __shfl_xor_sync(0xffffffffu, mx, o));
        float e1 = (lane < 48) ? expf(v1 - mx) : 0.f;
        float e2 = (lane + 32 < 48) ? expf(v2 - mx) : 0.f;
        float inv = 1.f / wsum(e1 + e2);
        if (lane < 48) sS[q][lane] = e1 * inv;
        if (lane + 32 < 48) sS[q][lane + 32] = e2 * inv;
    }
    __syncthreads();
    for (int i = tid; i < 48 * 32; i += 256) {
        int q = i >> 5, d = i & 31;
        float o = 0.f;
#pragma unroll
        for (int k = 0; k < 48; k++) o = fmaf(sS[q][k], sV[k][d], o);
        O[(size_t)(b * 48 + q) * DIM + h * 32 + d] = o;
    }
}

// ---------------- persistent decoder ----------------
__device__ __forceinline__ void gsync() {
    __syncthreads();
    if (threadIdx.x == 0) {
        __threadfence();
        unsigned gen = *(volatile unsigned*)&g_gen;
        if (atomicAdd(&g_cnt, 1u) == NB - 1u) {
            g_cnt = 0;
            __threadfence();
            *(volatile unsigned*)&g_gen = gen + 1u;
        } else {
            while (*(volatile unsigned*)&g_gen == gen) { }
        }
        __threadfence();
    }
    __syncthreads();
}

// 64x16 slice of C = A[64xK] @ W^T (+bias, relu). 256 thr stage, 64 compute.
__device__ void gemm16(const float* __restrict__ A, int ldA,
                       const float* __restrict__ W, int ldW,
                       const float* __restrict__ bias, float* __restrict__ C,
                       int N, int n0, int relu, float* sm) {
    float* sA = sm;             // 64*257
    float* sW = sm + 64 * 257;  // 16*257
    int tid = threadIdx.x;
    for (int i = tid; i < 64 * 256; i += 256)
        sA[(i >> 8) * 257 + (i & 255)] = A[(size_t)(i >> 8) * ldA + (i & 255)];
    for (int i = tid; i < 16 * 256; i += 256)
        sW[(i >> 8) * 257 + (i & 255)] = W[(size_t)(n0 + (i >> 8)) * ldW + (i & 255)];
    __syncthreads();
    if (tid < 64) {
        int m0 = (tid & 15) * 4, nq = (tid >> 4) * 4;
        const float* a0 = sA + m0 * 257;
        const float* w0 = sW + nq * 257;
        float acc[4][4] = {};
#pragma unroll 4
        for (int k = 0; k < 256; k++) {
            float a[4], w[4];
#pragma unroll
            for (int i = 0; i < 4; i++) a[i] = a0[i * 257 + k];
#pragma unroll
            for (int j = 0; j < 4; j++) w[j] = w0[j * 257 + k];
#pragma unroll
            for (int i = 0; i < 4; i++)
#pragma unroll
                for (int j = 0; j < 4; j++) acc[i][j] = fmaf(a[i], w[j], acc[i][j]);
        }
#pragma unroll
        for (int i = 0; i < 4; i++)
#pragma unroll
            for (int j = 0; j < 4; j++) {
                int n = n0 + nq + j;
                float c = acc[i][j] + (bias ? bias[n] : 0.f);
                if (relu) c = fmaxf(c, 0.f);
                C[(size_t)(m0 + i) * N + n] = c;
            }
    }
    __syncthreads();
}

__device__ float block_ln_val(float v, const float* __restrict__ w,
                              const float* __restrict__ b, float* sred) {
    int tid = threadIdx.x, lane = tid & 31, wd = tid >> 5;
    float s = wsum(v), q = wsum(v * v);
    __syncthreads();
    if (lane == 0) { sred[wd] = s; sred[8 + wd] = q; }
    __syncthreads();
    float S = 0.f, Q = 0.f;
#pragma unroll
    for (int i = 0; i < 8; i++) { S += sred[i]; Q += sred[8 + i]; }
    float m = S * (1.f / 256.f);
    float rs = rsqrtf(Q * (1.f / 256.f) - m * m + 1e-5f);
    return (v - m) * rs * w[tid] + b[tid];
}

// out[n] = dot(a[256], W[n][0..255]) + bias[n], each warp covers 32 n.
__device__ void warp_dot(const float* __restrict__ a, const float* __restrict__ W,
                         const float* __restrict__ bias, float* __restrict__ outp) {
    int h = threadIdx.x >> 5, lane = threadIdx.x & 31;
    float ar[8];
#pragma unroll
    for (int i = 0; i < 8; i++) ar[i] = a[lane + 32 * i];
#pragma unroll 2
    for (int nn = 0; nn < 32; nn++) {
        int n = h * 32 + nn;
        const float* wr = W + (size_t)n * 256;
        float s = 0.f;
#pragma unroll
        for (int i = 0; i < 8; i++) s = fmaf(ar[i], wr[lane + 32 * i], s);
        s = wsum(s);
        if (lane == 0) outp[n] = s + bias[n];
    }
}

__device__ void ph_att(int bi, int l, int p,
                       const float* s_wo, const float* s_bo,
                       const float* c_wqkv, const float* c_bqkv,
                       const float* c_wo, const float* c_bo,
                       const float* d_lnw, const float* d_lnb, float* sm) {
    float* sq = sm; float* satt = sm + 256; float* st = sm + 512; float* sy = sm + 768;
    float* sp = sm + 1024;    // 8*64
    float* sred = sm + 1536;  // 16
    int tid = threadIdx.x, h = tid >> 5, lane = tid & 31;
    const float* qkv = g_qkv + bi * 768;
    float* cache = g_skv + (size_t)(l * 64 + bi) * LT * 512;
    for (int i = tid; i < 512; i += 256) cache[(size_t)p * 512 + i] = qkv[256 + i];
    sq[tid] = qkv[tid];
    __syncthreads();
    const float sc = 0.17677669529663687f;
    float s1 = -1e30f, s2 = -1e30f;
    if (lane <= p) {
        const float* kr = cache + (size_t)lane * 512 + h * 32; float s = 0.f;
#pragma unroll
        for (int d = 0; d < 32; d++) s = fmaf(sq[h * 32 + d], kr[d], s);
        s1 = s * sc;
    }
    if (lane + 32 <= p) {
        const float* kr = cache + (size_t)(lane + 32) * 512 + h * 32; float s = 0.f;
#pragma unroll
        for (int d = 0; d < 32; d++) s = fmaf(sq[h * 32 + d], kr[d], s);
        s2 = s * sc;
    }
    float mx = fmaxf(s1, s2);
#pragma unroll
    for (int o = 16; o; o >>= 1) mx = fmaxf(mx, __shfl_xor_sync(0xffffffffu, mx, o));
    float e1 = (lane <= p) ? expf(s1 - mx) : 0.f;
    float e2 = (lane + 32 <= p) ? expf(s2 - mx) : 0.f;
    float inv = 1.f / wsum(e1 + e2);
    sp[h * 64 + lane] = e1 * inv; sp[h * 64 + lane + 32] = e2 * inv;
    __syncwarp();
    float o = 0.f;
    for (int j = 0; j <= p; j++)
        o = fmaf(sp[h * 64 + j], cache[(size_t)j * 512 + 256 + h * 32 + lane], o);
    satt[tid] = o;
    __syncthreads();
    warp_dot(satt, s_wo, s_bo, st);
    __syncthreads();
    float v = g_y[bi * 256 + tid] + st[tid];
    float y1 = block_ln_val(v, d_lnw + (l * 3) * 256, d_lnb + (l * 3) * 256, sred);
    sy[tid] = y1;
    __syncthreads();
    warp_dot(sy, c_wqkv, c_bqkv, sq);
    __syncthreads();
    const float* cb = g_ckv + ((size_t)l * 3072 + bi * 48) * 512;
    float c1, c2 = -1e30f;
    {
        const float* kr = cb + (size_t)lane * 512 + h * 32; float s = 0.f;
#pragma unroll
        for (int d = 0; d < 32; d++) s = fmaf(sq[h * 32 + d], kr[d], s);
        c1 = s * sc;
    }
    if (lane < 16) {
        const float* kr = cb + (size_t)(lane + 32) * 512 + h * 32; float s = 0.f;
#pragma unroll
        for (int d = 0; d < 32; d++) s = fmaf(sq[h * 32 + d], kr[d], s);
        c2 = s * sc;
    }
    mx = fmaxf(c1, c2);
#pragma unroll
    for (int o2 = 16; o2; o2 >>= 1) mx = fmaxf(mx, __shfl_xor_sync(0xffffffffu, mx, o2));
    e1 = expf(c1 - mx);
    e2 = (lane < 16) ? expf(c2 - mx) : 0.f;
    inv = 1.f / wsum(e1 + e2);
    sp[h * 64 + lane] = e1 * inv;
    if (lane < 16) sp[h * 64 + lane + 32] = e2 * inv;
    __syncwarp();
    o = 0.f;
#pragma unroll 4
    for (int j = 0; j < 48; j++)
        o = fmaf(sp[h * 64 + j], cb[(size_t)j * 512 + 256 + h * 32 + lane], o);
    satt[tid] = o;
    __syncthreads();
    warp_dot(satt, c_wo, c_bo, st);
    __syncthreads();
    v = sy[tid] + st[tid];
    float y2 = block_ln_val(v, d_lnw + (l * 3 + 1) * 256, d_lnb + (l * 3 + 1) * 256, sred);
    g_y[bi * 256 + tid] = y2;
}

__global__ void __launch_bounds__(256, 1) k_decoder(
    const float* __restrict__ emb, const float* __restrict__ head_w,
    const float* __restrict__ head_b,
    const float* __restrict__ s_wqkv, const float* __restrict__ s_bqkv,
    const float* __restrict__ s_wo, const float* __restrict__ s_bo,
    const float* __restrict__ c_wqkv, const float* __restrict__ c_bqkv,
    const float* __restrict__ c_wo, const float* __restrict__ c_bo,
    const float* __restrict__ dw1, const float* __restrict__ db1,
    const float* __restrict__ dw2, const float* __restrict__ db2,
    const float* __restrict__ d_lnw, const float* __restrict__ d_lnb,
    const float* __restrict__ lnf_w, const float* __restrict__ lnf_b,
    const float* __restrict__ sos, float* __restrict__ out) {
    extern __shared__ float sm[];
    int bi = blockIdx.x, tid = threadIdx.x;

    g_y[bi * 256 + tid] = sos[tid] + g_pe[tid];

    for (int p = 0; p < SEQ; p++) {
        for (int l = 0; l < NLAY; l++) {
            gsync();
            if (bi < 48)
                gemm16(g_y, 256, s_wqkv + (size_t)l * 768 * 256, 256,
                       s_bqkv + l * 768, g_qkv, 768, bi * 16, 0, sm);
            gsync();
            ph_att(bi, l, p, s_wo + (size_t)l * 65536, s_bo + l * 256,
                   c_wqkv + (size_t)l * 768 * 256, c_bqkv + l * 768,
                   c_wo + (size_t)l * 65536, c_bo + l * 256, d_lnw, d_lnb, sm);
            gsync();
            gemm16(g_y, 256, dw1 + (size_t)l * 1024 * 256, 256,
                   db1 + l * 1024, g_ff, 1024, bi * 16, 1, sm);
            gsync();
            {
                int kq = bi >> 4, ns = bi & 15;
                gemm16(g_ff + kq * 256, 1024,
                       dw2 + (size_t)l * 256 * 1024 + kq * 256, 1024,
                       (const float*)0, g_part + kq * 16384, 256, ns * 16, 0, sm);
            }
            gsync();
            {
                float t = db2[l * 256 + tid];
#pragma unroll
                for (int kq = 0; kq < 4; kq++) t += g_part[kq * 16384 + bi * 256 + tid];
                float v = g_y[bi * 256 + tid] + t;
                float y3 = block_ln_val(v, d_lnw + (l * 3 + 2) * 256,
                                        d_lnb + (l * 3 + 2) * 256, sm);
                g_y[bi * 256 + tid] = y3;
                if (l == NLAY - 1)
                    g_h[bi * 256 + tid] = block_ln_val(y3, lnf_w + 256, lnf_b + 256, sm);
                __syncthreads();
            }
        }
        gsync();
        float* lg = out + 3072 + (size_t)p * 65536;
        gemm16(g_h, 256, head_w + (size_t)p * 1024 * 256, 256,
               head_b + p * 1024, lg, 1024, bi * 16, 0, sm);
        gsync();
        {
            float* sv = sm; int* si = (int*)(sm + 256);
            unsigned k0 = g_keys[2 * p], k1 = g_keys[2 * p + 1];
            float best = -1e38f; int bidx = 0;
            const float* lgr = lg + (size_t)bi * 1024;
            for (int v = tid; v < 1024; v += 256) {
                // partitionable random_bits (32-bit): bits[i] = x ^ y of
                // threefry2x32(key, hi=0, lo=i)
                unsigned i = (unsigned)(bi * 1024 + v);
                uint2 r = tf2x32(k0, k1, 0u, i);
                unsigned bits = r.x ^ r.y;
                float f = __uint_as_float((bits >> 9) | 0x3f800000u) - 1.0f;
                f = fmaxf(f, 1.17549435e-38f);
                float g = -logf(-logf(f));
                float val = __fdiv_rn(lgr[v], 0.1f) + g;
                if (val > best) { best = val; bidx = v; }
            }
            sv[tid] = best; si[tid] = bidx;
            __syncthreads();
            for (int st = 128; st > 0; st >>= 1) {
                if (tid < st) {
                    float o = sv[tid + st];
                    if (o > sv[tid] || (o == sv[tid] && si[tid + st] < si[tid])) {
                        sv[tid] = o; si[tid] = si[tid + st];
                    }
                }
                __syncthreads();
            }
            int choice = si[0];
            if (tid == 0) {
                if (p < 32) out[bi * 32 + p] = (float)choice;
                else out[2048 + bi * 16 + (p - 32)] = (float)choice;
            }
            if (p < SEQ - 1)
                g_y[bi * 256 + tid] =
                    emb[((size_t)p * VOC + choice) * 256 + tid] + g_pe[(p + 1) * 256 + tid];
            __syncthreads();
        }
    }
}

// ---------------- launcher ----------------
extern "C" void kernel_launch(void* const* d_in, const int* in_sizes, int n_in,
                              void* d_out, int out_size) {
    const int*   x_cont = (const int*)d_in[0];
    const int*   x_cat  = (const int*)d_in[1];
    const float* sos    = (const float*)d_in[2];
    const float* emb    = (const float*)d_in[3];
    const float* head_w = (const float*)d_in[4];
    const float* head_b = (const float*)d_in[5];
    const float* e_wqkv = (const float*)d_in[6];
    const float* e_bqkv = (const float*)d_in[7];
    const float* e_wo   = (const float*)d_in[8];
    const float* e_bo   = (const float*)d_in[9];
    const float* e_w1   = (const float*)d_in[10];
    const float* e_b1   = (const float*)d_in[11];
    const float* e_w2   = (const float*)d_in[12];
    const float* e_b2   = (const float*)d_in[13];
    const float* e_lnw  = (const float*)d_in[14];
    const float* e_lnb  = (const float*)d_in[15];
    const float* s_wqkv = (const float*)d_in[16];
    const float* s_bqkv = (const float*)d_in[17];
    const float* s_wo   = (const float*)d_in[18];
    const float* s_bo   = (const float*)d_in[19];
    const float* c_wqkv = (const float*)d_in[20];
    const float* c_bqkv = (const float*)d_in[21];
    const float* c_wo   = (const float*)d_in[22];
    const float* c_bo   = (const float*)d_in[23];
    const float* dw1    = (const float*)d_in[24];
    const float* db1    = (const float*)d_in[25];
    const float* dw2    = (const float*)d_in[26];
    const float* db2    = (const float*)d_in[27];
    const float* d_lnw  = (const float*)d_in[28];
    const float* d_lnb  = (const float*)d_in[29];
    const float* lnf_w  = (const float*)d_in[30];
    const float* lnf_b  = (const float*)d_in[31];
    float* out = (float*)d_out;

#define SYM(p, s) float* p; cudaGetSymbolAddress((void**)&p, s)
    SYM(xA, g_xA); SYM(xB, g_xB); SYM(qkvE, g_qkvE); SYM(oE, g_oE); SYM(tE, g_tE);
    SYM(ffE, g_ffE); SYM(mem, g_mem); SYM(ckv, g_ckv);
#undef SYM

    auto gemm = [&](const float* A, const float* W, const float* B, float* C,
                    int M, int N, int K, int relu) {
        k_gemm<<<dim3(N / 64, M / 64), 256>>>(A, W, B, C, M, N, K, relu);
    };

    k_pe<<<49, 128>>>();
    k_keys<<<1, 64>>>();
    k_embed<<<3072, 256>>>(x_cont, x_cat, emb);

    for (int l = 0; l < NLAY; l++) {
        gemm(xA, e_wqkv + (size_t)l * 768 * 256, e_bqkv + l * 768, qkvE, 3072, 768, 256, 0);
        k_enc_attn<<<512, 256>>>(qkvE, oE);
        gemm(oE, e_wo + (size_t)l * 65536, e_bo + l * 256, tE, 3072, 256, 256, 0);
        k_addln<<<3072, 256>>>(xA, tE, e_lnw + (l * 2) * 256, e_lnb + (l * 2) * 256, xB);
        gemm(xB, e_w1 + (size_t)l * 1024 * 256, e_b1 + l * 1024, ffE, 3072, 1024, 256, 1);
        gemm(ffE, e_w2 + (size_t)l * 256 * 1024, e_b2 + l * 256, tE, 3072, 256, 1024, 0);
        k_addln<<<3072, 256>>>(xB, tE, e_lnw + (l * 2 + 1) * 256, e_lnb + (l * 2 + 1) * 256, xA);
    }
    k_addln<<<3072, 256>>>(xA, nullptr, lnf_w, lnf_b, mem);
    for (int l = 0; l < NLAY; l++)
        gemm(mem, c_wqkv + (size_t)l * 768 * 256 + 256 * 256, c_bqkv + l * 768 + 256,
             ckv + (size_t)l * 3072 * 512, 3072, 512, 256, 0);

    const int SMEMB = (64 * 257 + 16 * 257) * 4;
    cudaFuncSetAttribute(k_decoder, cudaFuncAttributeMaxDynamicSharedMemorySize, SMEMB);
    k_decoder<<<NB, 256, SMEMB>>>(emb, head_w, head_b,
                                  s_wqkv, s_bqkv, s_wo, s_bo,
                                  c_wqkv, c_bqkv, c_wo, c_bo,
                                  dw1, db1, dw2, db2,
                                  d_lnw, d_lnb, lnf_w, lnf_b, sos, out);
}

// round 8
// speedup vs baseline: 1.2240x; 1.2240x over previous
#include <cuda_runtime.h>
#include <cuda_bf16.h>
#include <math.h>
#include <stdint.h>

#define NLAY 6
#define DIM 256
#define VOC 1024
#define SEQ 48
#define BSZ 64
#define LT 49
#define NB 64          // persistent decoder blocks

__device__ float g_pe[LT * DIM];
__device__ unsigned g_keys[96];
__device__ float g_xA[3072 * DIM];
__device__ float g_xB[3072 * DIM];
__device__ float g_qkvE[3072 * 768];
__device__ float g_oE[3072 * DIM];
__device__ float g_tE[3072 * DIM];
__device__ float g_ffE[3072 * 1024];
__device__ float g_mem[3072 * DIM];
__device__ float g_ckv[NLAY * 3072 * 512];
__device__ float g_skv[(size_t)NLAY * BSZ * LT * 512];
__device__ float g_y[BSZ * DIM];
__device__ float g_qkv[BSZ * 768];
__device__ float g_ff[BSZ * 1024];
__device__ float g_part[4 * BSZ * DIM];
__device__ float g_h[BSZ * DIM];
__device__ unsigned g_cnt = 0;
__device__ unsigned g_gen = 0;

__device__ __forceinline__ float wsum(float s) {
#pragma unroll
    for (int o = 16; o; o >>= 1) s += __shfl_xor_sync(0xffffffffu, s, o);
    return s;
}

__device__ __forceinline__ uint2 tf2x32(unsigned k0, unsigned k1, unsigned x0, unsigned x1) {
    unsigned ks0 = k0, ks1 = k1, ks2 = k0 ^ k1 ^ 0x1BD11BDAu;
    x0 += ks0; x1 += ks1;
#define TFR(r) { x0 += x1; x1 = (x1 << (r)) | (x1 >> (32 - (r))); x1 ^= x0; }
    TFR(13) TFR(15) TFR(26) TFR(6)  x0 += ks1; x1 += ks2 + 1u;
    TFR(17) TFR(29) TFR(16) TFR(24) x0 += ks2; x1 += ks0 + 2u;
    TFR(13) TFR(15) TFR(26) TFR(6)  x0 += ks0; x1 += ks1 + 3u;
    TFR(17) TFR(29) TFR(16) TFR(24) x0 += ks1; x1 += ks2 + 4u;
    TFR(13) TFR(15) TFR(26) TFR(6)  x0 += ks2; x1 += ks0 + 5u;
#undef TFR
    return make_uint2(x0, x1);
}

// ---------------- setup / encoder kernels ----------------
__global__ void k_pe() {
    int p = blockIdx.x, j = threadIdx.x;
    float dv = expf((float)(2 * j) * (-logf(10000.0f) / 256.0f));
    float a = (float)p * dv;
    g_pe[p * DIM + 2 * j] = sinf(a);
    g_pe[p * DIM + 2 * j + 1] = cosf(a);
}

// jax_threefry_partitionable: split(key,48): subkey[j] = threefry(k1,k2, 0, j)
__global__ void k_keys() {
    int j = threadIdx.x;
    if (j < 48) {
        uint2 r = tf2x32(0u, 42u, 0u, (unsigned)j);
        g_keys[2 * j] = r.x; g_keys[2 * j + 1] = r.y;
    }
}

__global__ void k_embed(const int* __restrict__ xc, const int* __restrict__ xk,
                        const float* __restrict__ emb) {
    int row = blockIdx.x, t = threadIdx.x;
    int b = row / SEQ, s = row % SEQ;
    int idx = (s < 32) ? xc[b * 32 + s] : xk[b * 16 + (s - 32)];
    g_xA[(size_t)row * DIM + t] = emb[((size_t)s * VOC + idx) * DIM + t] + g_pe[s * DIM + t];
}

__global__ void k_gemm(const float* __restrict__ A, const float* __restrict__ W,
                       const float* __restrict__ bias, float* __restrict__ C,
                       int M, int N, int K, int relu) {
    __shared__ float sA[16][65], sB[16][65];
    int m0 = blockIdx.y * 64, n0 = blockIdx.x * 64;
    int tid = threadIdx.x;
    int r = tid >> 2, kk = (tid & 3) * 4;
    int ty = tid >> 4, tx = tid & 15;
    float acc[4][4] = {};
    for (int kb = 0; kb < K; kb += 16) {
        const float* Ap = A + (size_t)(m0 + r) * K + kb + kk;
        const float* Bp = W + (size_t)(n0 + r) * K + kb + kk;
#pragma unroll
        for (int u = 0; u < 4; u++) { sA[kk + u][r] = Ap[u]; sB[kk + u][r] = Bp[u]; }
        __syncthreads();
#pragma unroll
        for (int k = 0; k < 16; k++) {
            float a[4], b[4];
#pragma unroll
            for (int i = 0; i < 4; i++) a[i] = sA[k][ty * 4 + i];
#pragma unroll
            for (int j = 0; j < 4; j++) b[j] = sB[k][tx * 4 + j];
#pragma unroll
            for (int i = 0; i < 4; i++)
#pragma unroll
                for (int j = 0; j < 4; j++) acc[i][j] = fmaf(a[i], b[j], acc[i][j]);
        }
        __syncthreads();
    }
#pragma unroll
    for (int i = 0; i < 4; i++) {
        int m = m0 + ty * 4 + i;
#pragma unroll
        for (int j = 0; j < 4; j++) {
            int n = n0 + tx * 4 + j;
            float c = acc[i][j] + (bias ? bias[n] : 0.f);
            if (relu) c = fmaxf(c, 0.f);
            C[(size_t)m * N + n] = c;
        }
    }
}

__global__ void k_addln(const float* __restrict__ a, const float* __restrict__ b,
                        const float* __restrict__ w, const float* __restrict__ wb,
                        float* __restrict__ out) {
    int row = blockIdx.x, t = threadIdx.x;
    __shared__ float red[16];
    __shared__ float sm, srs;
    float v = a[(size_t)row * DIM + t] + (b ? b[(size_t)row * DIM + t] : 0.f);
    float s = wsum(v), q = wsum(v * v);
    int lane = t & 31, wd = t >> 5;
    if (lane == 0) { red[wd] = s; red[8 + wd] = q; }
    __syncthreads();
    if (t == 0) {
        float S = 0.f, Q = 0.f;
        for (int i = 0; i < 8; i++) { S += red[i]; Q += red[8 + i]; }
        float m = S * (1.f / 256.f);
        sm = m; srs = rsqrtf(Q * (1.f / 256.f) - m * m + 1e-5f);
    }
    __syncthreads();
    out[(size_t)row * DIM + t] = (v - sm) * srs * w[t] + wb[t];
}

__global__ void k_enc_attn(const float* __restrict__ QKV, float* __restrict__ O) {
    int b = blockIdx.x >> 3, h = blockIdx.x & 7, tid = threadIdx.x;
    __shared__ float sQ[48][33], sK[48][33], sV[48][33], sS[48][49];
    for (int i = tid; i < 48 * 32; i += 256) {
        int s = i >> 5, d = i & 31;
        size_t base = (size_t)(b * 48 + s) * 768;
        sQ[s][d] = QKV[base + h * 32 + d];
        sK[s][d] = QKV[base + 256 + h * 32 + d];
        sV[s][d] = QKV[base + 512 + h * 32 + d];
    }
    __syncthreads();
    const float sc = 0.17677669529663687f;
    for (int i = tid; i < 48 * 48; i += 256) {
        int q = i / 48, k = i % 48;
        float s = 0.f;
#pragma unroll
        for (int d = 0; d < 32; d++) s = fmaf(sQ[q][d], sK[k][d], s);
        sS[q][k] = s * sc;
    }
    __syncthreads();
    int lane = tid & 31, wd = tid >> 5;
    for (int q = wd; q < 48; q += 8) {
        float v1 = (lane < 48) ? sS[q][lane] : -1e30f;
        float v2 = (lane + 32 < 48) ? sS[q][lane + 32] : -1e30f;
        float mx = fmaxf(v1, v2);
#pragma unroll
        for (int o = 16; o; o >>= 1) mx = fmaxf(mx, __shfl_xor_sync(0xffffffffu, mx, o));
        float e1 = (lane < 48) ? expf(v1 - mx) : 0.f;
        float e2 = (lane + 32 < 48) ? expf(v2 - mx) : 0.f;
        float inv = 1.f / wsum(e1 + e2);
        if (lane < 48) sS[q][lane] = e1 * inv;
        if (lane + 32 < 48) sS[q][lane + 32] = e2 * inv;
    }
    __syncthreads();
    for (int i = tid; i < 48 * 32; i += 256) {
        int q = i >> 5, d = i & 31;
        float o = 0.f;
#pragma unroll
        for (int k = 0; k < 48; k++) o = fmaf(sS[q][k], sV[k][d], o);
        O[(size_t)(b * 48 + q) * DIM + h * 32 + d] = o;
    }
}

// ---------------- persistent decoder ----------------
__device__ __forceinline__ void gsync() {
    __syncthreads();
    if (threadIdx.x == 0) {
        __threadfence();
        unsigned gen = *(volatile unsigned*)&g_gen;
        if (atomicAdd(&g_cnt, 1u) == NB - 1u) {
            g_cnt = 0;
            __threadfence();
            *(volatile unsigned*)&g_gen = gen + 1u;
        } else {
            while (*(volatile unsigned*)&g_gen == gen) __nanosleep(200);
        }
        __threadfence();
    }
    __syncthreads();
}

// 64x16 slice of C = A[64xK] @ W^T (+bias, relu). 256 thr stage, 128 compute.
// Packed f32x2 FFMA2 inner loop; smem rows padded to 258 floats (even, 8B-aligned).
__device__ void gemm16(const float* __restrict__ A, int ldA,
                       const float* __restrict__ W, int ldW,
                       const float* __restrict__ bias, float* __restrict__ C,
                       int N, int n0, int relu, float* sm) {
    float* sA = sm;             // 64*258
    float* sW = sm + 64 * 258;  // 16*258
    int tid = threadIdx.x;
    for (int i = tid; i < 64 * 128; i += 256) {
        int r = i >> 7, k2 = i & 127;
        float2 v = *(const float2*)(A + (size_t)r * ldA + 2 * k2);
        *(float2*)(sA + r * 258 + 2 * k2) = v;
    }
    for (int i = tid; i < 16 * 128; i += 256) {
        int r = i >> 7, k2 = i & 127;
        float2 v = *(const float2*)(W + (size_t)(n0 + r) * ldW + 2 * k2);
        *(float2*)(sW + r * 258 + 2 * k2) = v;
    }
    __syncthreads();
    if (tid < 128) {
        int m0 = (tid & 15) * 4, nq = (tid >> 4) * 2;
        const float* a0 = sA + m0 * 258;
        const float* w0 = sW + nq * 258;
        unsigned long long acc[4][2] = {};
#pragma unroll 2
        for (int k2 = 0; k2 < 128; k2++) {
            unsigned long long a[4], w[2];
#pragma unroll
            for (int i = 0; i < 4; i++)
                a[i] = *(const unsigned long long*)(a0 + i * 258 + 2 * k2);
#pragma unroll
            for (int j = 0; j < 2; j++)
                w[j] = *(const unsigned long long*)(w0 + j * 258 + 2 * k2);
#pragma unroll
            for (int i = 0; i < 4; i++)
#pragma unroll
                for (int j = 0; j < 2; j++)
                    asm("fma.rn.f32x2 %0, %1, %2, %0;"
                        : "+l"(acc[i][j]) : "l"(a[i]), "l"(w[j]));
        }
#pragma unroll
        for (int i = 0; i < 4; i++)
#pragma unroll
            for (int j = 0; j < 2; j++) {
                int n = n0 + nq + j;
                float lo = __uint_as_float((unsigned)(acc[i][j] & 0xffffffffULL));
                float hi = __uint_as_float((unsigned)(acc[i][j] >> 32));
                float c = lo + hi + (bias ? bias[n] : 0.f);
                if (relu) c = fmaxf(c, 0.f);
                C[(size_t)(m0 + i) * N + n] = c;
            }
    }
    __syncthreads();
}

__device__ float block_ln_val(float v, const float* __restrict__ w,
                              const float* __restrict__ b, float* sred) {
    int tid = threadIdx.x, lane = tid & 31, wd = tid >> 5;
    float s = wsum(v), q = wsum(v * v);
    __syncthreads();
    if (lane == 0) { sred[wd] = s; sred[8 + wd] = q; }
    __syncthreads();
    float S = 0.f, Q = 0.f;
#pragma unroll
    for (int i = 0; i < 8; i++) { S += sred[i]; Q += sred[8 + i]; }
    float m = S * (1.f / 256.f);
    float rs = rsqrtf(Q * (1.f / 256.f) - m * m + 1e-5f);
    return (v - m) * rs * w[tid] + b[tid];
}

// out[n] = dot(a[256], W[n][0..255]) + bias[n], each warp covers 32 n.
__device__ void warp_dot(const float* __restrict__ a, const float* __restrict__ W,
                         const float* __restrict__ bias, float* __restrict__ outp) {
    int h = threadIdx.x >> 5, lane = threadIdx.x & 31;
    float ar[8];
#pragma unroll
    for (int i = 0; i < 8; i++) ar[i] = a[lane + 32 * i];
#pragma unroll 4
    for (int nn = 0; nn < 32; nn++) {
        int n = h * 32 + nn;
        const float* wr = W + (size_t)n * 256;
        float s = 0.f;
#pragma unroll
        for (int i = 0; i < 8; i++) s = fmaf(ar[i], wr[lane + 32 * i], s);
        s = wsum(s);
        if (lane == 0) outp[n] = s + bias[n];
    }
}

__device__ void ph_att(int bi, int l, int p,
                       const float* s_wo, const float* s_bo,
                       const float* c_wqkv, const float* c_bqkv,
                       const float* c_wo, const float* c_bo,
                       const float* d_lnw, const float* d_lnb, float* sm) {
    float* sq = sm; float* satt = sm + 256; float* st = sm + 512; float* sy = sm + 768;
    float* sp = sm + 1024;    // 8*64
    float* sred = sm + 1536;  // 16
    int tid = threadIdx.x, h = tid >> 5, lane = tid & 31;
    const float* qkv = g_qkv + bi * 768;
    float* cache = g_skv + (size_t)(l * 64 + bi) * LT * 512;
    for (int i = tid; i < 512; i += 256) cache[(size_t)p * 512 + i] = qkv[256 + i];
    sq[tid] = qkv[tid];
    __syncthreads();
    const float sc = 0.17677669529663687f;
    float s1 = -1e30f, s2 = -1e30f;
    if (lane <= p) {
        const float* kr = cache + (size_t)lane * 512 + h * 32; float s = 0.f;
#pragma unroll
        for (int d = 0; d < 32; d++) s = fmaf(sq[h * 32 + d], kr[d], s);
        s1 = s * sc;
    }
    if (lane + 32 <= p) {
        const float* kr = cache + (size_t)(lane + 32) * 512 + h * 32; float s = 0.f;
#pragma unroll
        for (int d = 0; d < 32; d++) s = fmaf(sq[h * 32 + d], kr[d], s);
        s2 = s * sc;
    }
    float mx = fmaxf(s1, s2);
#pragma unroll
    for (int o = 16; o; o >>= 1) mx = fmaxf(mx, __shfl_xor_sync(0xffffffffu, mx, o));
    float e1 = (lane <= p) ? expf(s1 - mx) : 0.f;
    float e2 = (lane + 32 <= p) ? expf(s2 - mx) : 0.f;
    float inv = 1.f / wsum(e1 + e2);
    sp[h * 64 + lane] = e1 * inv; sp[h * 64 + lane + 32] = e2 * inv;
    __syncwarp();
    {   // O = P @ V with 4-way MLP
        const float* vb = cache + 256 + h * 32 + lane;
        const float* pr = sp + h * 64;
        float o0 = 0.f, o1 = 0.f, o2 = 0.f, o3 = 0.f;
        int pe = p + 1, j = 0;
        for (; j + 4 <= pe; j += 4) {
            o0 = fmaf(pr[j],     vb[(size_t)(j) * 512],     o0);
            o1 = fmaf(pr[j + 1], vb[(size_t)(j + 1) * 512], o1);
            o2 = fmaf(pr[j + 2], vb[(size_t)(j + 2) * 512], o2);
            o3 = fmaf(pr[j + 3], vb[(size_t)(j + 3) * 512], o3);
        }
        for (; j < pe; j++) o0 = fmaf(pr[j], vb[(size_t)j * 512], o0);
        satt[tid] = (o0 + o1) + (o2 + o3);
    }
    __syncthreads();
    warp_dot(satt, s_wo, s_bo, st);
    __syncthreads();
    float v = g_y[bi * 256 + tid] + st[tid];
    float y1 = block_ln_val(v, d_lnw + (l * 3) * 256, d_lnb + (l * 3) * 256, sred);
    sy[tid] = y1;
    __syncthreads();
    warp_dot(sy, c_wqkv, c_bqkv, sq);
    __syncthreads();
    const float* cb = g_ckv + ((size_t)l * 3072 + bi * 48) * 512;
    float c1, c2 = -1e30f;
    {
        const float* kr = cb + (size_t)lane * 512 + h * 32; float s = 0.f;
#pragma unroll
        for (int d = 0; d < 32; d++) s = fmaf(sq[h * 32 + d], kr[d], s);
        c1 = s * sc;
    }
    if (lane < 16) {
        const float* kr = cb + (size_t)(lane + 32) * 512 + h * 32; float s = 0.f;
#pragma unroll
        for (int d = 0; d < 32; d++) s = fmaf(sq[h * 32 + d], kr[d], s);
        c2 = s * sc;
    }
    mx = fmaxf(c1, c2);
#pragma unroll
    for (int o2x = 16; o2x; o2x >>= 1) mx = fmaxf(mx, __shfl_xor_sync(0xffffffffu, mx, o2x));
    e1 = expf(c1 - mx);
    e2 = (lane < 16) ? expf(c2 - mx) : 0.f;
    inv = 1.f / wsum(e1 + e2);
    sp[h * 64 + lane] = e1 * inv;
    if (lane < 16) sp[h * 64 + lane + 32] = e2 * inv;
    __syncwarp();
    {   // cross O = P @ V, 4-way MLP, 48 iters exactly
        const float* vb = cb + 256 + h * 32 + lane;
        const float* pr = sp + h * 64;
        float o0 = 0.f, o1 = 0.f, o2 = 0.f, o3 = 0.f;
#pragma unroll 3
        for (int j = 0; j < 48; j += 4) {
            o0 = fmaf(pr[j],     vb[(size_t)(j) * 512],     o0);
            o1 = fmaf(pr[j + 1], vb[(size_t)(j + 1) * 512], o1);
            o2 = fmaf(pr[j + 2], vb[(size_t)(j + 2) * 512], o2);
            o3 = fmaf(pr[j + 3], vb[(size_t)(j + 3) * 512], o3);
        }
        satt[tid] = (o0 + o1) + (o2 + o3);
    }
    __syncthreads();
    warp_dot(satt, c_wo, c_bo, st);
    __syncthreads();
    v = sy[tid] + st[tid];
    float y2 = block_ln_val(v, d_lnw + (l * 3 + 1) * 256, d_lnb + (l * 3 + 1) * 256, sred);
    g_y[bi * 256 + tid] = y2;
}

__global__ void __launch_bounds__(256, 1) k_decoder(
    const float* __restrict__ emb, const float* __restrict__ head_w,
    const float* __restrict__ head_b,
    const float* __restrict__ s_wqkv, const float* __restrict__ s_bqkv,
    const float* __restrict__ s_wo, const float* __restrict__ s_bo,
    const float* __restrict__ c_wqkv, const float* __restrict__ c_bqkv,
    const float* __restrict__ c_wo, const float* __restrict__ c_bo,
    const float* __restrict__ dw1, const float* __restrict__ db1,
    const float* __restrict__ dw2, const float* __restrict__ db2,
    const float* __restrict__ d_lnw, const float* __restrict__ d_lnb,
    const float* __restrict__ lnf_w, const float* __restrict__ lnf_b,
    const float* __restrict__ sos, float* __restrict__ out) {
    extern __shared__ float sm[];
    int bi = blockIdx.x, tid = threadIdx.x;

    g_y[bi * 256 + tid] = sos[tid] + g_pe[tid];

    for (int p = 0; p < SEQ; p++) {
        for (int l = 0; l < NLAY; l++) {
            gsync();
            if (bi < 48)
                gemm16(g_y, 256, s_wqkv + (size_t)l * 768 * 256, 256,
                       s_bqkv + l * 768, g_qkv, 768, bi * 16, 0, sm);
            gsync();
            ph_att(bi, l, p, s_wo + (size_t)l * 65536, s_bo + l * 256,
                   c_wqkv + (size_t)l * 768 * 256, c_bqkv + l * 768,
                   c_wo + (size_t)l * 65536, c_bo + l * 256, d_lnw, d_lnb, sm);
            gsync();
            gemm16(g_y, 256, dw1 + (size_t)l * 1024 * 256, 256,
                   db1 + l * 1024, g_ff, 1024, bi * 16, 1, sm);
            gsync();
            {
                int kq = bi >> 4, ns = bi & 15;
                gemm16(g_ff + kq * 256, 1024,
                       dw2 + (size_t)l * 256 * 1024 + kq * 256, 1024,
                       (const float*)0, g_part + kq * 16384, 256, ns * 16, 0, sm);
            }
            gsync();
            {
                float t = db2[l * 256 + tid];
#pragma unroll
                for (int kq = 0; kq < 4; kq++) t += g_part[kq * 16384 + bi * 256 + tid];
                float v = g_y[bi * 256 + tid] + t;
                float y3 = block_ln_val(v, d_lnw + (l * 3 + 2) * 256,
                                        d_lnb + (l * 3 + 2) * 256, sm);
                g_y[bi * 256 + tid] = y3;
                if (l == NLAY - 1)
                    g_h[bi * 256 + tid] = block_ln_val(y3, lnf_w + 256, lnf_b + 256, sm);
                __syncthreads();
            }
        }
        gsync();
        float* lg = out + 3072 + (size_t)p * 65536;
        gemm16(g_h, 256, head_w + (size_t)p * 1024 * 256, 256,
               head_b + p * 1024, lg, 1024, bi * 16, 0, sm);
        gsync();
        {
            float* sv = sm; int* si = (int*)(sm + 256);
            unsigned k0 = g_keys[2 * p], k1 = g_keys[2 * p + 1];
            float best = -1e38f; int bidx = 0;
            const float* lgr = lg + (size_t)bi * 1024;
            for (int v = tid; v < 1024; v += 256) {
                // partitionable random_bits (32-bit): bits[i] = x ^ y of
                // threefry2x32(key, hi=0, lo=i)
                unsigned i = (unsigned)(bi * 1024 + v);
                uint2 r = tf2x32(k0, k1, 0u, i);
                unsigned bits = r.x ^ r.y;
                float f = __uint_as_float((bits >> 9) | 0x3f800000u) - 1.0f;
                f = fmaxf(f, 1.17549435e-38f);
                float g = -logf(-logf(f));
                float val = __fdiv_rn(lgr[v], 0.1f) + g;
                if (val > best) { best = val; bidx = v; }
            }
            sv[tid] = best; si[tid] = bidx;
            __syncthreads();
            for (int st = 128; st > 0; st >>= 1) {
                if (tid < st) {
                    float o = sv[tid + st];
                    if (o > sv[tid] || (o == sv[tid] && si[tid + st] < si[tid])) {
                        sv[tid] = o; si[tid] = si[tid + st];
                    }
                }
                __syncthreads();
            }
            int choice = si[0];
            if (tid == 0) {
                if (p < 32) out[bi * 32 + p] = (float)choice;
                else out[2048 + bi * 16 + (p - 32)] = (float)choice;
            }
            if (p < SEQ - 1)
                g_y[bi * 256 + tid] =
                    emb[((size_t)p * VOC + choice) * 256 + tid] + g_pe[(p + 1) * 256 + tid];
            __syncthreads();
        }
    }
}

// ---------------- launcher ----------------
extern "C" void kernel_launch(void* const* d_in, const int* in_sizes, int n_in,
                              void* d_out, int out_size) {
    const int*   x_cont = (const int*)d_in[0];
    const int*   x_cat  = (const int*)d_in[1];
    const float* sos    = (const float*)d_in[2];
    const float* emb    = (const float*)d_in[3];
    const float* head_w = (const float*)d_in[4];
    const float* head_b = (const float*)d_in[5];
    const float* e_wqkv = (const float*)d_in[6];
    const float* e_bqkv = (const float*)d_in[7];
    const float* e_wo   = (const float*)d_in[8];
    const float* e_bo   = (const float*)d_in[9];
    const float* e_w1   = (const float*)d_in[10];
    const float* e_b1   = (const float*)d_in[11];
    const float* e_w2   = (const float*)d_in[12];
    const float* e_b2   = (const float*)d_in[13];
    const float* e_lnw  = (const float*)d_in[14];
    const float* e_lnb  = (const float*)d_in[15];
    const float* s_wqkv = (const float*)d_in[16];
    const float* s_bqkv = (const float*)d_in[17];
    const float* s_wo   = (const float*)d_in[18];
    const float* s_bo   = (const float*)d_in[19];
    const float* c_wqkv = (const float*)d_in[20];
    const float* c_bqkv = (const float*)d_in[21];
    const float* c_wo   = (const float*)d_in[22];
    const float* c_bo   = (const float*)d_in[23];
    const float* dw1    = (const float*)d_in[24];
    const float* db1    = (const float*)d_in[25];
    const float* dw2    = (const float*)d_in[26];
    const float* db2    = (const float*)d_in[27];
    const float* d_lnw  = (const float*)d_in[28];
    const float* d_lnb  = (const float*)d_in[29];
    const float* lnf_w  = (const float*)d_in[30];
    const float* lnf_b  = (const float*)d_in[31];
    float* out = (float*)d_out;

#define SYM(p, s) float* p; cudaGetSymbolAddress((void**)&p, s)
    SYM(xA, g_xA); SYM(xB, g_xB); SYM(qkvE, g_qkvE); SYM(oE, g_oE); SYM(tE, g_tE);
    SYM(ffE, g_ffE); SYM(mem, g_mem); SYM(ckv, g_ckv);
#undef SYM

    auto gemm = [&](const float* A, const float* W, const float* B, float* C,
                    int M, int N, int K, int relu) {
        k_gemm<<<dim3(N / 64, M / 64), 256>>>(A, W, B, C, M, N, K, relu);
    };

    k_pe<<<49, 128>>>();
    k_keys<<<1, 64>>>();
    k_embed<<<3072, 256>>>(x_cont, x_cat, emb);

    for (int l = 0; l < NLAY; l++) {
        gemm(xA, e_wqkv + (size_t)l * 768 * 256, e_bqkv + l * 768, qkvE, 3072, 768, 256, 0);
        k_enc_attn<<<512, 256>>>(qkvE, oE);
        gemm(oE, e_wo + (size_t)l * 65536, e_bo + l * 256, tE, 3072, 256, 256, 0);
        k_addln<<<3072, 256>>>(xA, tE, e_lnw + (l * 2) * 256, e_lnb + (l * 2) * 256, xB);
        gemm(xB, e_w1 + (size_t)l * 1024 * 256, e_b1 + l * 1024, ffE, 3072, 1024, 256, 1);
        gemm(ffE, e_w2 + (size_t)l * 256 * 1024, e_b2 + l * 256, tE, 3072, 256, 1024, 0);
        k_addln<<<3072, 256>>>(xB, tE, e_lnw + (l * 2 + 1) * 256, e_lnb + (l * 2 + 1) * 256, xA);
    }
    k_addln<<<3072, 256>>>(xA, nullptr, lnf_w, lnf_b, mem);
    for (int l = 0; l < NLAY; l++)
        gemm(mem, c_wqkv + (size_t)l * 768 * 256 + 256 * 256, c_bqkv + l * 768 + 256,
             ckv + (size_t)l * 3072 * 512, 3072, 512, 256, 0);

    const int SMEMB = (64 * 258 + 16 * 258) * 4;
    cudaFuncSetAttribute(k_decoder, cudaFuncAttributeMaxDynamicSharedMemorySize, SMEMB);
    k_decoder<<<NB, 256, SMEMB>>>(emb, head_w, head_b,
                                  s_wqkv, s_bqkv, s_wo, s_bo,
                                  c_wqkv, c_bqkv, c_wo, c_bo,
                                  dw1, db1, dw2, db2,
                                  d_lnw, d_lnb, lnf_w, lnf_b, sos, out);
}